// round 14
// baseline (speedup 1.0000x reference)
#include <cuda_runtime.h>
#include <cuda_fp16.h>
#include <cstdint>

#define T_STEPS 256
#define BATCH   64
#define XDIM    512
#define HDIM    2048
#define G4      8192
#define NCTAS   128
#define PTHREADS 512
#define KT      64                 // K-tile per stage (halfs) = 128 B rows
#define PSTAGES 6                  // persistent-kernel stages
#define ASTG    8192               // persistent stage tile bytes (64 rows * 128 B)
#define GSTR    68                 // gsum row stride (halfs)
#define GSLAB   (64*GSTR)          // halfs per slab (8704 B)

// persistent smem layout (bytes): gsum ALIASES stage memory (offset 0)
#define OFF_SB   (2*PSTAGES*ASTG)            // 98304
#define PSMEM    (4*PSTAGES*ASTG)            // 196608 B total

// xproj v2: 128x128 tiles, 512 threads
#define X2THREADS 512
#define XNST    4
#define XASTG   16384
#define XGSTR   132
#define XGSLAB  (128*XGSTR)
#define X2OFF_B (XNST*XASTG)
#define X2OFF_G (2*XNST*XASTG)
#define X2SMEM  (X2OFF_G + 2*XGSLAB*2)

// ---------------- device scratch ----------------
__device__ __align__(16) __half d_in16 [T_STEPS * BATCH * XDIM];
__device__ __align__(16) __half d_wih16[G4 * XDIM];
__device__ __align__(16) __half d_whh16[G4 * HDIM];
__device__ __align__(16) float  d_bsum [G4];
__device__ __align__(16) __half d_xproj[(size_t)T_STEPS * BATCH * G4];
__device__ __align__(16) __half d_h16  [2][BATCH * HDIM];
__device__ __align__(16) float  d_sum  [T_STEPS * BATCH];
__device__ unsigned d_bar;

// ---------------- helpers ----------------
__device__ __forceinline__ void mma16816(float* c,
    uint32_t a0, uint32_t a1, uint32_t a2, uint32_t a3,
    uint32_t b0, uint32_t b1)
{
    asm volatile(
        "mma.sync.aligned.m16n8k16.row.col.f32.f16.f16.f32 "
        "{%0,%1,%2,%3},{%4,%5,%6,%7},{%8,%9},{%0,%1,%2,%3};\n"
        : "+f"(c[0]), "+f"(c[1]), "+f"(c[2]), "+f"(c[3])
        : "r"(a0), "r"(a1), "r"(a2), "r"(a3), "r"(b0), "r"(b1));
}
#define LDSM4(r0, r1, r2, r3, addr) \
    asm volatile("ldmatrix.sync.aligned.m8n8.x4.shared.b16 {%0,%1,%2,%3}, [%4];" \
        : "=r"(r0), "=r"(r1), "=r"(r2), "=r"(r3) : "r"(addr))

__device__ __forceinline__ float tanh_hw(float x) {
    float y;
    asm("tanh.approx.f32 %0, %1;" : "=f"(y) : "f"(x));
    return y;
}
__device__ __forceinline__ float sigmoid_hw(float x) {
    return fmaf(tanh_hw(0.5f * x), 0.5f, 0.5f);
}
__device__ __forceinline__ float exp_hw(float x) {
    float y;
    asm("ex2.approx.ftz.f32 %0, %1;" : "=f"(y) : "f"(x * 1.4426950408889634f));
    return y;
}

__device__ __forceinline__ uint32_t smem_u32(const void* p) {
    return (uint32_t)__cvta_generic_to_shared(p);
}
__device__ __forceinline__ int fperm(int r) { return ((r & 1) << 2) | ((r & 7) >> 1); }

#define CP16(dst_u32, src_ptr) \
    asm volatile("cp.async.cg.shared.global [%0], [%1], 16;\n" :: "r"(dst_u32), "l"(src_ptr))
#define CP_COMMIT() asm volatile("cp.async.commit_group;\n" ::: "memory")
#define CP_WAIT2()  asm volatile("cp.async.wait_group 2;\n" ::: "memory")
#define CP_WAIT4()  asm volatile("cp.async.wait_group 4;\n" ::: "memory")

// row permutation: dst row (CTA-major: cta*64 + gate*16 + jj) -> src gate row
__device__ __forceinline__ int perm_src_row(int r) {
    int cta = r >> 6;
    int ln  = r & 63;
    int gate = ln >> 4;
    int jj   = ln & 15;
    return gate * HDIM + cta * 16 + jj;
}

// ---------------- phase 0 ----------------
__global__ __launch_bounds__(256) void prep_kernel(
    const float* __restrict__ input, const float* __restrict__ h0,
    const float* __restrict__ c0,    const float* __restrict__ wih,
    const float* __restrict__ whh,   const float* __restrict__ bih,
    const float* __restrict__ bhh)
{
    (void)c0;
    const int i0 = blockIdx.x * blockDim.x + threadIdx.x;
    const int stride = gridDim.x * blockDim.x;
    if (i0 == 0) d_bar = 0u;
    for (int i = i0; i < T_STEPS * BATCH * XDIM; i += stride)
        d_in16[i] = __float2half(input[i]);
    for (int i = i0; i < G4 * XDIM; i += stride) {
        int r = i >> 9, k = i & (XDIM - 1);
        d_wih16[i] = __float2half(wih[perm_src_row(r) * XDIM + k]);
    }
    for (int i = i0; i < G4 * HDIM; i += stride) {
        int r = i >> 11, k = i & (HDIM - 1);
        d_whh16[i] = __float2half(whh[(size_t)perm_src_row(r) * HDIM + k]);
    }
    for (int i = i0; i < G4; i += stride) {
        int s = perm_src_row(i);
        d_bsum[i] = bih[s] + bhh[s];
    }
    for (int i = i0; i < BATCH * HDIM; i += stride)
        d_h16[0][i] = __float2half(h0[i]);
    for (int i = i0; i < T_STEPS * BATCH; i += stride)
        d_sum[i] = 0.0f;
}

// ---------------- phase 1: xproj v2 (identical to R13) ----------------
__global__ __launch_bounds__(X2THREADS) void xproj_kernel()
{
    extern __shared__ __align__(1024) char xsmem_raw[];
    const uint32_t sbase = smem_u32(xsmem_raw);
    const uint32_t sA = sbase;
    const uint32_t sB = sbase + X2OFF_B;
    __half* gsum = (__half*)(xsmem_raw + X2OFF_G);

    const int tid  = threadIdx.x;
    const int lane = tid & 31;
    const int gwid = tid >> 5;
    const int wm = gwid & 1;
    const int wn = (gwid >> 1) & 3;
    const int wk = gwid >> 3;
    const int n0 = blockIdx.x * 128;
    const int m0 = blockIdx.y * 128;

    const int lrow = tid >> 2, lch = tid & 3;
    const int fp_s = fperm(lrow);
    const uint32_t d0 = (uint32_t)(lrow * 128 + ((lch ^ fp_s) << 4));
    const uint32_t d1 = (uint32_t)(lrow * 128 + (((lch + 4) ^ fp_s) << 4));
    const int scol = lch * 8;
    const __half* Ag = d_in16  + (size_t)(m0 + lrow) * XDIM + scol;
    const __half* Bg = d_wih16 + (size_t)(n0 + lrow) * XDIM + scol;

    const int fp_l = fperm(lane & 7);
    uint32_t rowA[4];
    #pragma unroll
    for (int mf = 0; mf < 4; ++mf)
        rowA[mf] = (uint32_t)((wm * 64 + mf * 16 + (lane & 15)) * 128);
    const uint32_t rowB0 = (uint32_t)((wn * 32 + ((lane >> 4) & 1) * 8 + (lane & 7)) * 128);
    const uint32_t rowB1 = rowB0 + 16 * 128;
    const int khA = (lane >> 4) & 1;
    const int khB = (lane >> 3) & 1;
    const int kb16 = wk * 2;

    float acc[4][4][4];
    #pragma unroll
    for (int i = 0; i < 4; i++)
        #pragma unroll
        for (int j = 0; j < 4; j++)
            #pragma unroll
            for (int q = 0; q < 4; q++) acc[i][j][q] = 0.0f;

#define XISSUE(SLOT, KB) do {                                                 \
        const uint32_t ao_ = sA + (uint32_t)(SLOT) * XASTG;                   \
        const uint32_t bo_ = sB + (uint32_t)(SLOT) * XASTG;                   \
        CP16(ao_ + d0, Ag + (KB));                                            \
        CP16(ao_ + d1, Ag + (KB) + 32);                                       \
        CP16(bo_ + d0, Bg + (KB));                                            \
        CP16(bo_ + d1, Bg + (KB) + 32);                                       \
        CP_COMMIT();                                                          \
    } while (0)

    #pragma unroll
    for (int st = 0; st < 3; ++st) XISSUE(st, st * KT);

    const int NITX = XDIM / KT;
    #pragma unroll
    for (int it = 0; it < NITX; ++it) {
        CP_WAIT2();
        __syncthreads();
        const uint32_t At = sA + (uint32_t)((it & 3) * XASTG);
        const uint32_t Bt = sB + (uint32_t)((it & 3) * XASTG);
        #pragma unroll
        for (int kc = 0; kc < 2; ++kc) {
            const uint32_t ccA = (uint32_t)((((kb16 + kc) << 1) | khA) ^ fp_l) << 4;
            const uint32_t ccB = (uint32_t)((((kb16 + kc) << 1) | khB) ^ fp_l) << 4;
            uint32_t a[4][4], bb0[4], bb1[4];
            #pragma unroll
            for (int mf = 0; mf < 4; ++mf)
                LDSM4(a[mf][0], a[mf][1], a[mf][2], a[mf][3], At + rowA[mf] + ccA);
            LDSM4(bb0[0], bb0[1], bb0[2], bb0[3], Bt + rowB0 + ccB);
            LDSM4(bb1[0], bb1[1], bb1[2], bb1[3], Bt + rowB1 + ccB);
            #pragma unroll
            for (int mf = 0; mf < 4; ++mf) {
                mma16816(acc[mf][0], a[mf][0], a[mf][1], a[mf][2], a[mf][3], bb0[0], bb0[1]);
                mma16816(acc[mf][1], a[mf][0], a[mf][1], a[mf][2], a[mf][3], bb0[2], bb0[3]);
                mma16816(acc[mf][2], a[mf][0], a[mf][1], a[mf][2], a[mf][3], bb1[0], bb1[1]);
                mma16816(acc[mf][3], a[mf][0], a[mf][1], a[mf][2], a[mf][3], bb1[2], bb1[3]);
            }
        }
        __syncthreads();
        if (it + 3 < NITX) {
            XISSUE((it + 3) & 3, (it + 3) * KT);
        } else {
            CP_COMMIT();
        }
    }
#undef XISSUE

    {
        __half* gs = gsum + (size_t)wk * XGSLAB;
        const int gq = lane >> 2, tq = lane & 3;
        #pragma unroll
        for (int mf = 0; mf < 4; ++mf) {
            const int row = wm * 64 + mf * 16 + gq;
            #pragma unroll
            for (int nf = 0; nf < 4; ++nf) {
                const int col = wn * 32 + nf * 8 + tq * 2;
                *(__half2*)&gs[row * XGSTR + col] =
                    __floats2half2_rn(acc[mf][nf][0], acc[mf][nf][1]);
                *(__half2*)&gs[(row + 8) * XGSTR + col] =
                    __floats2half2_rn(acc[mf][nf][2], acc[mf][nf][3]);
            }
        }
    }
    __syncthreads();

    {
        const int r  = tid >> 2;
        const int c0 = (tid & 3) * 32;
        const __half* g0 = gsum + (size_t)r * XGSTR + c0;
        const __half* g1 = g0 + XGSLAB;
        __half* dst = d_xproj + (size_t)(m0 + r) * G4 + n0 + c0;
        const float* bs = d_bsum + n0 + c0;
        #pragma unroll
        for (int j = 0; j < 16; ++j) {
            float2 v0 = __half22float2(*(const __half2*)(g0 + 2 * j));
            float2 v1 = __half22float2(*(const __half2*)(g1 + 2 * j));
            float2 bb = *(const float2*)(bs + 2 * j);
            *(__half2*)(dst + 2 * j) =
                __floats2half2_rn(v0.x + v1.x + bb.x, v0.y + v1.y + bb.y);
        }
    }
}

// ---------------- grid barrier (128 CTAs co-resident) ----------------
__device__ __forceinline__ void grid_barrier(unsigned target)
{
    __syncthreads();
    if (threadIdx.x == 0) {
        __threadfence();
        atomicAdd(&d_bar, 1u);
        volatile unsigned* p = &d_bar;
        while (*p < target) { }
        __threadfence();
    }
    __syncthreads();
}

// ---------------- phase 2: persistent kernel — 1m x 2n x 4k retile ----------
__global__ __launch_bounds__(PTHREADS, 1) void lstm_persistent_c0(
    float* __restrict__ out, const float* __restrict__ c0)
{
    extern __shared__ __align__(1024) char smem_raw[];
    const uint32_t sbase = smem_u32(smem_raw);
    __half* gsum = (__half*)smem_raw;          // ALIASES stage memory (safe: see ordering)

    const int cta  = blockIdx.x;
    const int tid  = threadIdx.x;
    const int lane = tid & 31;
    const int g    = tid >> 8;              // K-half group (0,1)
    const int gtid = tid & 255;
    const int gwid = gtid >> 5;             // warp in group 0..7
    const int wn   = gwid & 1;              // n half (32 gate cols)
    const int wk4  = gwid >> 1;             // k16 quarter within stage (0..3)
    const int gq = lane >> 2, tq = lane & 3;
    const int n0 = cta * 64;                // permuted gate-row base
    const int KOFF = g * (HDIM / 2);
    const int NIT  = (HDIM / 2) / KT;       // 16

    const uint32_t aGrp = sbase + (uint32_t)g * PSTAGES * ASTG;
    const uint32_t bGrp = sbase + OFF_SB + (uint32_t)g * PSTAGES * ASTG;

    const int lrow = gtid >> 2, lch = gtid & 3;
    const int fp_s = fperm(lrow);
    const uint32_t d0 = (uint32_t)(lrow * 128 + ((lch ^ fp_s) << 4));
    const uint32_t d1 = (uint32_t)(lrow * 128 + (((lch + 4) ^ fp_s) << 4));
    const int scol = lch * 8;
    const __half* Bg = d_whh16 + (size_t)(n0 + lrow) * HDIM + KOFF + scol;

    // ldmatrix addressing — loop-invariant (wk4 fixed per warp)
    const int fp_l = fperm(lane & 7);
    const int khA = (lane >> 4) & 1;
    const int khB = (lane >> 3) & 1;
    const uint32_t ccA = (uint32_t)(((wk4 << 1) | khA) ^ fp_l) << 4;
    const uint32_t ccB = (uint32_t)(((wk4 << 1) | khB) ^ fp_l) << 4;
    uint32_t rowA[4];
    #pragma unroll
    for (int mf = 0; mf < 4; ++mf)
        rowA[mf] = (uint32_t)((mf * 16 + (lane & 15)) * 128) + ccA;
    const uint32_t rowB0 = (uint32_t)((wn * 32 + ((lane >> 4) & 1) * 8 + (lane & 7)) * 128) + ccB;
    const uint32_t rowB1 = rowB0 + 16 * 128;

    const size_t HOFF = (size_t)T_STEPS * BATCH * HDIM;
    const size_t COFF = HOFF + (size_t)BATCH * HDIM;

    const int b1 = tid >> 4,        jj1 = tid & 15;
    const int b2 = 32 + (tid >> 4), jj2 = jj1;
    float creg1 = c0[b1 * HDIM + cta * 16 + jj1];
    float creg2 = c0[b2 * HDIM + cta * 16 + jj2];

    float pe1 = 0.0f, pe2 = 0.0f;
    unsigned bar_target = 0;

#define ISSUE(SLOT, KB, HB) do {                                              \
        const __half* asrc_ = (HB) + (size_t)lrow * HDIM + KOFF + (KB) + scol;\
        const __half* bsrc_ = Bg + (KB);                                      \
        const uint32_t ao_ = aGrp + (uint32_t)(SLOT) * ASTG;                  \
        const uint32_t bo_ = bGrp + (uint32_t)(SLOT) * ASTG;                  \
        CP16(ao_ + d0, asrc_);                                                \
        CP16(ao_ + d1, asrc_ + 32);                                           \
        CP16(bo_ + d0, bsrc_);                                                \
        CP16(bo_ + d1, bsrc_ + 32);                                           \
        CP_COMMIT();                                                          \
    } while (0)

    {
        const __half* hbuf = d_h16[0];
        #pragma unroll
        for (int st = 0; st < 5; ++st) ISSUE(st, st * KT, hbuf);
    }

    #pragma unroll 1
    for (int t = 0; t < T_STEPS; ++t) {
        const __half* hbuf = d_h16[t & 1];

        // prefetch xproj gate values (hidden behind GEMM)
        const __half* xp = d_xproj + (size_t)t * BATCH * G4 + n0;
        const __half* xr1 = xp + (size_t)b1 * G4;
        const __half* xr2 = xp + (size_t)b2 * G4;
        float xv1[4], xv2[4];
        #pragma unroll
        for (int q = 0; q < 4; ++q) {
            xv1[q] = __half2float(xr1[q * 16 + jj1]);
            xv2[q] = __half2float(xr2[q * 16 + jj2]);
        }

        float acc[4][4][4];   // [mf][nf][reg] — m64 x n32 per warp
        #pragma unroll
        for (int i = 0; i < 4; i++)
            #pragma unroll
            for (int j = 0; j < 4; j++)
                #pragma unroll
                for (int q = 0; q < 4; q++) acc[i][j][q] = 0.0f;

        #pragma unroll
        for (int it = 0; it < NIT; ++it) {
            const int slot = it % PSTAGES;          // const-folded (full unroll)
            CP_WAIT4();
            asm volatile("bar.sync %0, 256;\n" :: "r"(g + 1) : "memory");
            const uint32_t At = aGrp + (uint32_t)(slot * ASTG);
            const uint32_t Bt = bGrp + (uint32_t)(slot * ASTG);
            uint32_t a[4][4], bb0[4], bb1[4];
            #pragma unroll
            for (int mf = 0; mf < 4; ++mf)
                LDSM4(a[mf][0], a[mf][1], a[mf][2], a[mf][3], At + rowA[mf]);
            LDSM4(bb0[0], bb0[1], bb0[2], bb0[3], Bt + rowB0);
            LDSM4(bb1[0], bb1[1], bb1[2], bb1[3], Bt + rowB1);
            #pragma unroll
            for (int mf = 0; mf < 4; ++mf) {
                mma16816(acc[mf][0], a[mf][0], a[mf][1], a[mf][2], a[mf][3], bb0[0], bb0[1]);
                mma16816(acc[mf][1], a[mf][0], a[mf][1], a[mf][2], a[mf][3], bb0[2], bb0[3]);
                mma16816(acc[mf][2], a[mf][0], a[mf][1], a[mf][2], a[mf][3], bb1[0], bb1[1]);
                mma16816(acc[mf][3], a[mf][0], a[mf][1], a[mf][2], a[mf][3], bb1[2], bb1[3]);
            }
            if (it + 5 < NIT) {
                const int wslot = (it + 5) % PSTAGES;   // const-folded
                ISSUE(wslot, (it + 5) * KT, hbuf);
            } else {
                CP_COMMIT();
            }
        }

        // all LDSM reads of stage memory done before slabs overwrite it
        __syncthreads();

        // slab write (fp16): slab = g*4 + wk4 (8 slabs, aliased over stages)
        {
            __half* gs = gsum + (size_t)(g * 4 + wk4) * GSLAB;
            #pragma unroll
            for (int mf = 0; mf < 4; ++mf) {
                const int row = mf * 16 + gq;
                #pragma unroll
                for (int nf = 0; nf < 4; ++nf) {
                    const int col = wn * 32 + nf * 8 + tq * 2;
                    *(__half2*)&gs[row * GSTR + col] =
                        __floats2half2_rn(acc[mf][nf][0], acc[mf][nf][1]);
                    *(__half2*)&gs[(row + 8) * GSTR + col] =
                        __floats2half2_rn(acc[mf][nf][2], acc[mf][nf][3]);
                }
            }
        }
        __syncthreads();

        // pointwise LSTM + exp (8-slab reduction)
        __half* hN = d_h16[(t + 1) & 1];
        float e1, e2;
        {
            const __half* gb = gsum + (size_t)b1 * GSTR;
            float ip = xv1[0], fpv = xv1[1], gp = xv1[2], op = xv1[3];
            #pragma unroll
            for (int s = 0; s < 8; ++s) {
                const __half* gs = gb + (size_t)s * GSLAB;
                ip  += __half2float(gs[jj1]);
                fpv += __half2float(gs[16 + jj1]);
                gp  += __half2float(gs[32 + jj1]);
                op  += __half2float(gs[48 + jj1]);
            }
            float ii = sigmoid_hw(ip), ff = sigmoid_hw(fpv);
            float gg = tanh_hw(gp),    oo = sigmoid_hw(op);
            float cn = ff * creg1 + ii * gg;
            creg1 = cn;
            float hn = oo * tanh_hw(cn);
            hN[b1 * HDIM + cta * 16 + jj1] = __float2half(hn);
            if (t == T_STEPS - 1) {
                out[HOFF + (size_t)b1 * HDIM + cta * 16 + jj1] = hn;
                out[COFF + (size_t)b1 * HDIM + cta * 16 + jj1] = cn;
            }
            e1 = exp_hw(hn);
        }
        {
            const __half* gb = gsum + (size_t)b2 * GSTR;
            float ip = xv2[0], fpv = xv2[1], gp = xv2[2], op = xv2[3];
            #pragma unroll
            for (int s = 0; s < 8; ++s) {
                const __half* gs = gb + (size_t)s * GSLAB;
                ip  += __half2float(gs[jj2]);
                fpv += __half2float(gs[16 + jj2]);
                gp  += __half2float(gs[32 + jj2]);
                op  += __half2float(gs[48 + jj2]);
            }
            float ii = sigmoid_hw(ip), ff = sigmoid_hw(fpv);
            float gg = tanh_hw(gp),    oo = sigmoid_hw(op);
            float cn = ff * creg2 + ii * gg;
            creg2 = cn;
            float hn = oo * tanh_hw(cn);
            hN[b2 * HDIM + cta * 16 + jj2] = __float2half(hn);
            if (t == T_STEPS - 1) {
                out[HOFF + (size_t)b2 * HDIM + cta * 16 + jj2] = hn;
                out[COFF + (size_t)b2 * HDIM + cta * 16 + jj2] = cn;
            }
            e2 = exp_hw(hn);
        }
        float v1 = e1, v2 = e2;
        #pragma unroll
        for (int o = 8; o > 0; o >>= 1) {
            v1 += __shfl_xor_sync(0xffffffffu, v1, o);
            v2 += __shfl_xor_sync(0xffffffffu, v2, o);
        }

        bar_target += NCTAS;
        grid_barrier(bar_target);    // pointwise reads done before prologue overwrites slabs

        if (t + 1 < T_STEPS) {
            const __half* hnext = d_h16[(t + 1) & 1];
            #pragma unroll
            for (int st = 0; st < 5; ++st) ISSUE(st, st * KT, hnext);
        }
        if (t > 0) {
            float s1 = __ldcg(&d_sum[(t - 1) * BATCH + b1]);
            float s2 = __ldcg(&d_sum[(t - 1) * BATCH + b2]);
            out[(size_t)(t - 1) * BATCH * HDIM + (size_t)b1 * HDIM + cta * 16 + jj1] = pe1 * (1.0f / s1);
            out[(size_t)(t - 1) * BATCH * HDIM + (size_t)b2 * HDIM + cta * 16 + jj2] = pe2 * (1.0f / s2);
        }
        if ((lane & 15) == 0) {
            atomicAdd(&d_sum[t * BATCH + b1], v1);
            atomicAdd(&d_sum[t * BATCH + b2], v2);
        }
        pe1 = e1;
        pe2 = e2;
    }

    bar_target += NCTAS;
    grid_barrier(bar_target);
    {
        float s1 = __ldcg(&d_sum[(T_STEPS - 1) * BATCH + b1]);
        float s2 = __ldcg(&d_sum[(T_STEPS - 1) * BATCH + b2]);
        out[(size_t)(T_STEPS - 1) * BATCH * HDIM + (size_t)b1 * HDIM + cta * 16 + jj1] = pe1 * (1.0f / s1);
        out[(size_t)(T_STEPS - 1) * BATCH * HDIM + (size_t)b2 * HDIM + cta * 16 + jj2] = pe2 * (1.0f / s2);
    }
#undef ISSUE
}

// ---------------- entry ----------------
extern "C" void kernel_launch(void* const* d_in, const int* in_sizes, int n_in,
                              void* d_out, int out_size)
{
    (void)in_sizes; (void)n_in; (void)out_size;
    const float* input = (const float*)d_in[0];
    const float* h0    = (const float*)d_in[1];
    const float* c0    = (const float*)d_in[2];
    const float* wih   = (const float*)d_in[3];
    const float* whh   = (const float*)d_in[4];
    const float* bih   = (const float*)d_in[5];
    const float* bhh   = (const float*)d_in[6];

    cudaFuncSetAttribute(xproj_kernel,
                         cudaFuncAttributeMaxDynamicSharedMemorySize, X2SMEM);
    cudaFuncSetAttribute(lstm_persistent_c0,
                         cudaFuncAttributeMaxDynamicSharedMemorySize, PSMEM);

    prep_kernel<<<1024, 256>>>(input, h0, c0, wih, whh, bih, bhh);
    xproj_kernel<<<dim3(G4 / 128, (T_STEPS * BATCH) / 128), X2THREADS, X2SMEM>>>();
    lstm_persistent_c0<<<NCTAS, PTHREADS, PSMEM>>>((float*)d_out, c0);
}

// round 15
// speedup vs baseline: 1.0255x; 1.0255x over previous
#include <cuda_runtime.h>
#include <cuda_fp16.h>
#include <cstdint>

#define T_STEPS 256
#define BATCH   64
#define XDIM    512
#define HDIM    2048
#define G4      8192
#define NCTAS   128
#define PTHREADS 512
#define KT      64                 // K-tile per stage (halfs) = 128 B rows
#define PSTAGES 6                  // persistent-kernel stages
#define ASTG    8192               // persistent stage tile bytes (64 rows * 128 B)
#define GSTR    68                 // persistent gsum row stride (halfs)
#define GSLAB   (64*GSTR)          // halfs per slab

// persistent smem layout (bytes)
#define OFF_SB   (2*PSTAGES*ASTG)            // 98304
#define OFF_GSUM (OFF_SB + 2*PSTAGES*ASTG)   // 196608
#define PSMEM    (OFF_GSUM + 4*GSLAB*2)      // 231424 B

// xproj v2: 128x128 tiles, 512 threads
#define X2THREADS 512
#define XNST    4
#define XASTG   16384
#define XGSTR   132
#define XGSLAB  (128*XGSTR)
#define X2OFF_B (XNST*XASTG)
#define X2OFF_G (2*XNST*XASTG)
#define X2SMEM  (X2OFF_G + 2*XGSLAB*2)

// ---------------- device scratch ----------------
__device__ __align__(16) __half d_in16 [T_STEPS * BATCH * XDIM];
__device__ __align__(16) __half d_wih16[G4 * XDIM];
__device__ __align__(16) __half d_whh16[G4 * HDIM];
__device__ __align__(16) float  d_bsum [G4];
__device__ __align__(16) __half d_xproj[(size_t)T_STEPS * BATCH * G4];
__device__ __align__(16) __half d_h16  [2][BATCH * HDIM];
__device__ __align__(16) float  d_sum  [T_STEPS * BATCH];
__device__ unsigned d_bar;

// ---------------- helpers ----------------
__device__ __forceinline__ void mma16816(float* c,
    uint32_t a0, uint32_t a1, uint32_t a2, uint32_t a3,
    uint32_t b0, uint32_t b1)
{
    asm volatile(
        "mma.sync.aligned.m16n8k16.row.col.f32.f16.f16.f32 "
        "{%0,%1,%2,%3},{%4,%5,%6,%7},{%8,%9},{%0,%1,%2,%3};\n"
        : "+f"(c[0]), "+f"(c[1]), "+f"(c[2]), "+f"(c[3])
        : "r"(a0), "r"(a1), "r"(a2), "r"(a3), "r"(b0), "r"(b1));
}
#define LDSM4(r0, r1, r2, r3, addr) \
    asm volatile("ldmatrix.sync.aligned.m8n8.x4.shared.b16 {%0,%1,%2,%3}, [%4];" \
        : "=r"(r0), "=r"(r1), "=r"(r2), "=r"(r3) : "r"(addr))

__device__ __forceinline__ float tanh_hw(float x) {
    float y;
    asm("tanh.approx.f32 %0, %1;" : "=f"(y) : "f"(x));
    return y;
}
__device__ __forceinline__ float sigmoid_hw(float x) {
    return fmaf(tanh_hw(0.5f * x), 0.5f, 0.5f);
}
__device__ __forceinline__ float exp_hw(float x) {
    float y;
    asm("ex2.approx.ftz.f32 %0, %1;" : "=f"(y) : "f"(x * 1.4426950408889634f));
    return y;
}

__device__ __forceinline__ uint32_t smem_u32(const void* p) {
    return (uint32_t)__cvta_generic_to_shared(p);
}
__device__ __forceinline__ int fperm(int r) { return ((r & 1) << 2) | ((r & 7) >> 1); }

#define CP16(dst_u32, src_ptr) \
    asm volatile("cp.async.cg.shared.global [%0], [%1], 16;\n" :: "r"(dst_u32), "l"(src_ptr))
#define CP_COMMIT() asm volatile("cp.async.commit_group;\n" ::: "memory")
#define CP_WAIT2()  asm volatile("cp.async.wait_group 2;\n" ::: "memory")
#define CP_WAIT4()  asm volatile("cp.async.wait_group 4;\n" ::: "memory")

// row permutation: dst row (CTA-major: cta*64 + gate*16 + jj) -> src gate row
__device__ __forceinline__ int perm_src_row(int r) {
    int cta = r >> 6;
    int ln  = r & 63;
    int gate = ln >> 4;
    int jj   = ln & 15;
    return gate * HDIM + cta * 16 + jj;
}

__device__ __forceinline__ uint2 cvt4(const float4 v) {
    __half2 p0 = __floats2half2_rn(v.x, v.y);
    __half2 p1 = __floats2half2_rn(v.z, v.w);
    return make_uint2(*(uint32_t*)&p0, *(uint32_t*)&p1);
}

// ---------------- phase 0 (vectorized conversions) ----------------
__global__ __launch_bounds__(256) void prep_kernel(
    const float* __restrict__ input, const float* __restrict__ h0,
    const float* __restrict__ c0,    const float* __restrict__ wih,
    const float* __restrict__ whh,   const float* __restrict__ bih,
    const float* __restrict__ bhh)
{
    (void)c0;
    const int i0 = blockIdx.x * blockDim.x + threadIdx.x;
    const int stride = gridDim.x * blockDim.x;
    if (i0 == 0) d_bar = 0u;
    // input: contiguous, 4-wide
    for (int i = i0; i < (T_STEPS * BATCH * XDIM) / 4; i += stride)
        *(uint2*)(d_in16 + i * 4) = cvt4(*(const float4*)(input + i * 4));
    // wih: permuted rows, 4 consecutive k stay in one row (XDIM % 4 == 0)
    for (int i = i0; i < (G4 * XDIM) / 4; i += stride) {
        int e = i * 4;
        int r = e >> 9, k = e & (XDIM - 1);
        *(uint2*)(d_wih16 + e) =
            cvt4(*(const float4*)(wih + (size_t)perm_src_row(r) * XDIM + k));
    }
    // whh: permuted rows, 4-wide (HDIM % 4 == 0)
    for (int i = i0; i < (G4 * HDIM) / 4; i += stride) {
        size_t e = (size_t)i * 4;
        int r = (int)(e >> 11), k = (int)(e & (HDIM - 1));
        *(uint2*)(d_whh16 + e) =
            cvt4(*(const float4*)(whh + (size_t)perm_src_row(r) * HDIM + k));
    }
    for (int i = i0; i < G4; i += stride) {
        int s = perm_src_row(i);
        d_bsum[i] = bih[s] + bhh[s];
    }
    // h0: contiguous, 4-wide
    for (int i = i0; i < (BATCH * HDIM) / 4; i += stride)
        *(uint2*)(&d_h16[0][i * 4]) = cvt4(*(const float4*)(h0 + i * 4));
    for (int i = i0; i < T_STEPS * BATCH; i += stride)
        d_sum[i] = 0.0f;
}

// ---------------- phase 1: xproj v2 — 128x128 tiles, m2 x n4 x k2 ----------------
__global__ __launch_bounds__(X2THREADS) void xproj_kernel()
{
    extern __shared__ __align__(1024) char xsmem_raw[];
    const uint32_t sbase = smem_u32(xsmem_raw);
    const uint32_t sA = sbase;
    const uint32_t sB = sbase + X2OFF_B;
    __half* gsum = (__half*)(xsmem_raw + X2OFF_G);

    const int tid  = threadIdx.x;
    const int lane = tid & 31;
    const int gwid = tid >> 5;              // 0..15
    const int wm = gwid & 1;                // m half (64 rows)
    const int wn = (gwid >> 1) & 3;         // n quarter (32 cols)
    const int wk = gwid >> 3;               // k half within stage
    const int n0 = blockIdx.x * 128;
    const int m0 = blockIdx.y * 128;

    const int lrow = tid >> 2, lch = tid & 3;
    const int fp_s = fperm(lrow);
    const uint32_t d0 = (uint32_t)(lrow * 128 + ((lch ^ fp_s) << 4));
    const uint32_t d1 = (uint32_t)(lrow * 128 + (((lch + 4) ^ fp_s) << 4));
    const int scol = lch * 8;
    const __half* Ag = d_in16  + (size_t)(m0 + lrow) * XDIM + scol;
    const __half* Bg = d_wih16 + (size_t)(n0 + lrow) * XDIM + scol;

    const int fp_l = fperm(lane & 7);
    uint32_t rowA[4];
    #pragma unroll
    for (int mf = 0; mf < 4; ++mf)
        rowA[mf] = (uint32_t)((wm * 64 + mf * 16 + (lane & 15)) * 128);
    const uint32_t rowB0 = (uint32_t)((wn * 32 + ((lane >> 4) & 1) * 8 + (lane & 7)) * 128);
    const uint32_t rowB1 = rowB0 + 16 * 128;
    const int khA = (lane >> 4) & 1;
    const int khB = (lane >> 3) & 1;
    const int kb16 = wk * 2;

    float acc[4][4][4];   // [mf][nf][reg]
    #pragma unroll
    for (int i = 0; i < 4; i++)
        #pragma unroll
        for (int j = 0; j < 4; j++)
            #pragma unroll
            for (int q = 0; q < 4; q++) acc[i][j][q] = 0.0f;

#define XISSUE(SLOT, KB) do {                                                 \
        const uint32_t ao_ = sA + (uint32_t)(SLOT) * XASTG;                   \
        const uint32_t bo_ = sB + (uint32_t)(SLOT) * XASTG;                   \
        CP16(ao_ + d0, Ag + (KB));                                            \
        CP16(ao_ + d1, Ag + (KB) + 32);                                       \
        CP16(bo_ + d0, Bg + (KB));                                            \
        CP16(bo_ + d1, Bg + (KB) + 32);                                       \
        CP_COMMIT();                                                          \
    } while (0)

    #pragma unroll
    for (int st = 0; st < 3; ++st) XISSUE(st, st * KT);

    const int NITX = XDIM / KT;   // 8
    #pragma unroll
    for (int it = 0; it < NITX; ++it) {
        CP_WAIT2();
        __syncthreads();
        const uint32_t At = sA + (uint32_t)((it & 3) * XASTG);
        const uint32_t Bt = sB + (uint32_t)((it & 3) * XASTG);
        #pragma unroll
        for (int kc = 0; kc < 2; ++kc) {
            const uint32_t ccA = (uint32_t)((((kb16 + kc) << 1) | khA) ^ fp_l) << 4;
            const uint32_t ccB = (uint32_t)((((kb16 + kc) << 1) | khB) ^ fp_l) << 4;
            uint32_t a[4][4], bb0[4], bb1[4];
            #pragma unroll
            for (int mf = 0; mf < 4; ++mf)
                LDSM4(a[mf][0], a[mf][1], a[mf][2], a[mf][3], At + rowA[mf] + ccA);
            LDSM4(bb0[0], bb0[1], bb0[2], bb0[3], Bt + rowB0 + ccB);
            LDSM4(bb1[0], bb1[1], bb1[2], bb1[3], Bt + rowB1 + ccB);
            #pragma unroll
            for (int mf = 0; mf < 4; ++mf) {
                mma16816(acc[mf][0], a[mf][0], a[mf][1], a[mf][2], a[mf][3], bb0[0], bb0[1]);
                mma16816(acc[mf][1], a[mf][0], a[mf][1], a[mf][2], a[mf][3], bb0[2], bb0[3]);
                mma16816(acc[mf][2], a[mf][0], a[mf][1], a[mf][2], a[mf][3], bb1[0], bb1[1]);
                mma16816(acc[mf][3], a[mf][0], a[mf][1], a[mf][2], a[mf][3], bb1[2], bb1[3]);
            }
        }
        __syncthreads();
        if (it + 3 < NITX) {
            XISSUE((it + 3) & 3, (it + 3) * KT);
        } else {
            CP_COMMIT();
        }
    }
#undef XISSUE

    {
        __half* gs = gsum + (size_t)wk * XGSLAB;
        const int gq = lane >> 2, tq = lane & 3;
        #pragma unroll
        for (int mf = 0; mf < 4; ++mf) {
            const int row = wm * 64 + mf * 16 + gq;
            #pragma unroll
            for (int nf = 0; nf < 4; ++nf) {
                const int col = wn * 32 + nf * 8 + tq * 2;
                *(__half2*)&gs[row * XGSTR + col] =
                    __floats2half2_rn(acc[mf][nf][0], acc[mf][nf][1]);
                *(__half2*)&gs[(row + 8) * XGSTR + col] =
                    __floats2half2_rn(acc[mf][nf][2], acc[mf][nf][3]);
            }
        }
    }
    __syncthreads();

    {
        const int r  = tid >> 2;
        const int c0 = (tid & 3) * 32;
        const __half* g0 = gsum + (size_t)r * XGSTR + c0;
        const __half* g1 = g0 + XGSLAB;
        __half* dst = d_xproj + (size_t)(m0 + r) * G4 + n0 + c0;
        const float* bs = d_bsum + n0 + c0;
        #pragma unroll
        for (int j = 0; j < 16; ++j) {
            float2 v0 = __half22float2(*(const __half2*)(g0 + 2 * j));
            float2 v1 = __half22float2(*(const __half2*)(g1 + 2 * j));
            float2 bb = *(const float2*)(bs + 2 * j);
            *(__half2*)(dst + 2 * j) =
                __floats2half2_rn(v0.x + v1.x + bb.x, v0.y + v1.y + bb.y);
        }
    }
}

// ---------------- grid barrier (128 CTAs co-resident) ----------------
__device__ __forceinline__ void grid_barrier(unsigned target)
{
    __syncthreads();
    if (threadIdx.x == 0) {
        __threadfence();
        atomicAdd(&d_bar, 1u);
        volatile unsigned* p = &d_bar;
        while (*p < target) { }
        __threadfence();
    }
    __syncthreads();
}

// ---------------- phase 2: persistent recurrent kernel (R13 exact) ----------
__global__ __launch_bounds__(PTHREADS, 1) void lstm_persistent_c0(
    float* __restrict__ out, const float* __restrict__ c0)
{
    extern __shared__ __align__(1024) char smem_raw[];
    const uint32_t sbase = smem_u32(smem_raw);
    __half* gsum = (__half*)(smem_raw + OFF_GSUM);

    const int cta  = blockIdx.x;
    const int tid  = threadIdx.x;
    const int lane = tid & 31;
    const int g    = tid >> 8;
    const int gtid = tid & 255;
    const int gwid = gtid >> 5;
    const int wm = gwid & 1;
    const int wn = (gwid >> 1) & 1;
    const int wk = gwid >> 2;
    const int gq = lane >> 2, tq = lane & 3;
    const int n0 = cta * 64;
    const int KOFF = g * (HDIM / 2);
    const int NIT  = (HDIM / 2) / KT;

    const uint32_t aGrp = sbase + (uint32_t)g * PSTAGES * ASTG;
    const uint32_t bGrp = sbase + OFF_SB + (uint32_t)g * PSTAGES * ASTG;

    const int lrow = gtid >> 2, lch = gtid & 3;
    const int fp_s = fperm(lrow);
    const uint32_t d0 = (uint32_t)(lrow * 128 + ((lch ^ fp_s) << 4));
    const uint32_t d1 = (uint32_t)(lrow * 128 + (((lch + 4) ^ fp_s) << 4));
    const int scol = lch * 8;
    const __half* Bg = d_whh16 + (size_t)(n0 + lrow) * HDIM + KOFF + scol;

    const int fp_l = fperm(lane & 7);
    const uint32_t rowA0 = (uint32_t)((wm * 32 + (lane & 15)) * 128);
    const uint32_t rowA1 = rowA0 + 16 * 128;
    const uint32_t rowB0 = (uint32_t)((wn * 32 + ((lane >> 4) & 1) * 8 + (lane & 7)) * 128);
    const uint32_t rowB1 = rowB0 + 16 * 128;
    const int khA = (lane >> 4) & 1;
    const int khB = (lane >> 3) & 1;
    const int kb16 = wk * 2;

    const size_t HOFF = (size_t)T_STEPS * BATCH * HDIM;
    const size_t COFF = HOFF + (size_t)BATCH * HDIM;

    const int b1 = tid >> 4,        jj1 = tid & 15;
    const int b2 = 32 + (tid >> 4), jj2 = jj1;
    float creg1 = c0[b1 * HDIM + cta * 16 + jj1];
    float creg2 = c0[b2 * HDIM + cta * 16 + jj2];

    float pe1 = 0.0f, pe2 = 0.0f;
    unsigned bar_target = 0;

#define ISSUE(SLOT, KB, HB) do {                                              \
        const __half* asrc_ = (HB) + (size_t)lrow * HDIM + KOFF + (KB) + scol;\
        const __half* bsrc_ = Bg + (KB);                                      \
        const uint32_t ao_ = aGrp + (uint32_t)(SLOT) * ASTG;                  \
        const uint32_t bo_ = bGrp + (uint32_t)(SLOT) * ASTG;                  \
        CP16(ao_ + d0, asrc_);                                                \
        CP16(ao_ + d1, asrc_ + 32);                                           \
        CP16(bo_ + d0, bsrc_);                                                \
        CP16(bo_ + d1, bsrc_ + 32);                                           \
        CP_COMMIT();                                                          \
    } while (0)

    {
        const __half* hbuf = d_h16[0];
        #pragma unroll
        for (int st = 0; st < 5; ++st) ISSUE(st, st * KT, hbuf);
    }

    #pragma unroll 1
    for (int t = 0; t < T_STEPS; ++t) {
        const __half* hbuf = d_h16[t & 1];

        const __half* xp = d_xproj + (size_t)t * BATCH * G4 + n0;
        const __half* xr1 = xp + (size_t)b1 * G4;
        const __half* xr2 = xp + (size_t)b2 * G4;
        float xv1[4], xv2[4];
        #pragma unroll
        for (int q = 0; q < 4; ++q) {
            xv1[q] = __half2float(xr1[q * 16 + jj1]);
            xv2[q] = __half2float(xr2[q * 16 + jj2]);
        }

        float acc[2][4][4];
        #pragma unroll
        for (int i = 0; i < 2; i++)
            #pragma unroll
            for (int j = 0; j < 4; j++)
                #pragma unroll
                for (int q = 0; q < 4; q++) acc[i][j][q] = 0.0f;

        #pragma unroll
        for (int it = 0; it < NIT; ++it) {
            const int slot = it % PSTAGES;          // const-folded
            CP_WAIT4();
            asm volatile("bar.sync %0, 256;\n" :: "r"(g + 1) : "memory");
            const uint32_t At = aGrp + (uint32_t)(slot * ASTG);
            const uint32_t Bt = bGrp + (uint32_t)(slot * ASTG);
            #pragma unroll
            for (int kc = 0; kc < 2; ++kc) {
                const uint32_t ccA = (uint32_t)((((kb16 + kc) << 1) | khA) ^ fp_l) << 4;
                const uint32_t ccB = (uint32_t)((((kb16 + kc) << 1) | khB) ^ fp_l) << 4;
                uint32_t a0[4], a1[4], bb0[4], bb1[4];
                LDSM4(a0[0], a0[1], a0[2], a0[3], At + rowA0 + ccA);
                LDSM4(a1[0], a1[1], a1[2], a1[3], At + rowA1 + ccA);
                LDSM4(bb0[0], bb0[1], bb0[2], bb0[3], Bt + rowB0 + ccB);
                LDSM4(bb1[0], bb1[1], bb1[2], bb1[3], Bt + rowB1 + ccB);
                mma16816(acc[0][0], a0[0], a0[1], a0[2], a0[3], bb0[0], bb0[1]);
                mma16816(acc[0][1], a0[0], a0[1], a0[2], a0[3], bb0[2], bb0[3]);
                mma16816(acc[0][2], a0[0], a0[1], a0[2], a0[3], bb1[0], bb1[1]);
                mma16816(acc[0][3], a0[0], a0[1], a0[2], a0[3], bb1[2], bb1[3]);
                mma16816(acc[1][0], a1[0], a1[1], a1[2], a1[3], bb0[0], bb0[1]);
                mma16816(acc[1][1], a1[0], a1[1], a1[2], a1[3], bb0[2], bb0[3]);
                mma16816(acc[1][2], a1[0], a1[1], a1[2], a1[3], bb1[0], bb1[1]);
                mma16816(acc[1][3], a1[0], a1[1], a1[2], a1[3], bb1[2], bb1[3]);
            }
            if (it + 5 < NIT) {
                const int wslot = (it + 5) % PSTAGES;   // const-folded
                ISSUE(wslot, (it + 5) * KT, hbuf);
            } else {
                CP_COMMIT();
            }
        }

        {
            __half* gs = gsum + (size_t)(g * 2 + wk) * GSLAB;
            #pragma unroll
            for (int mf = 0; mf < 2; ++mf) {
                const int row = wm * 32 + mf * 16 + gq;
                #pragma unroll
                for (int nf = 0; nf < 4; ++nf) {
                    const int col = wn * 32 + nf * 8 + tq * 2;
                    *(__half2*)&gs[row * GSTR + col] =
                        __floats2half2_rn(acc[mf][nf][0], acc[mf][nf][1]);
                    *(__half2*)&gs[(row + 8) * GSTR + col] =
                        __floats2half2_rn(acc[mf][nf][2], acc[mf][nf][3]);
                }
            }
        }
        __syncthreads();

        __half* hN = d_h16[(t + 1) & 1];
        float e1, e2;
        {
            const __half* gb = gsum + (size_t)b1 * GSTR;
            float ip = __half2float(gb[jj1]) + __half2float(gb[GSLAB + jj1])
                     + __half2float(gb[2*GSLAB + jj1]) + __half2float(gb[3*GSLAB + jj1]) + xv1[0];
            float fpv= __half2float(gb[16+jj1]) + __half2float(gb[GSLAB+16+jj1])
                     + __half2float(gb[2*GSLAB+16+jj1]) + __half2float(gb[3*GSLAB+16+jj1]) + xv1[1];
            float gp = __half2float(gb[32+jj1]) + __half2float(gb[GSLAB+32+jj1])
                     + __half2float(gb[2*GSLAB+32+jj1]) + __half2float(gb[3*GSLAB+32+jj1]) + xv1[2];
            float op = __half2float(gb[48+jj1]) + __half2float(gb[GSLAB+48+jj1])
                     + __half2float(gb[2*GSLAB+48+jj1]) + __half2float(gb[3*GSLAB+48+jj1]) + xv1[3];
            float ii = sigmoid_hw(ip), ff = sigmoid_hw(fpv);
            float gg = tanh_hw(gp),    oo = sigmoid_hw(op);
            float cn = ff * creg1 + ii * gg;
            creg1 = cn;
            float hn = oo * tanh_hw(cn);
            hN[b1 * HDIM + cta * 16 + jj1] = __float2half(hn);
            if (t == T_STEPS - 1) {
                out[HOFF + (size_t)b1 * HDIM + cta * 16 + jj1] = hn;
                out[COFF + (size_t)b1 * HDIM + cta * 16 + jj1] = cn;
            }
            e1 = exp_hw(hn);
        }
        {
            const __half* gb = gsum + (size_t)b2 * GSTR;
            float ip = __half2float(gb[jj2]) + __half2float(gb[GSLAB + jj2])
                     + __half2float(gb[2*GSLAB + jj2]) + __half2float(gb[3*GSLAB + jj2]) + xv2[0];
            float fpv= __half2float(gb[16+jj2]) + __half2float(gb[GSLAB+16+jj2])
                     + __half2float(gb[2*GSLAB+16+jj2]) + __half2float(gb[3*GSLAB+16+jj2]) + xv2[1];
            float gp = __half2float(gb[32+jj2]) + __half2float(gb[GSLAB+32+jj2])
                     + __half2float(gb[2*GSLAB+32+jj2]) + __half2float(gb[3*GSLAB+32+jj2]) + xv2[2];
            float op = __half2float(gb[48+jj2]) + __half2float(gb[GSLAB+48+jj2])
                     + __half2float(gb[2*GSLAB+48+jj2]) + __half2float(gb[3*GSLAB+48+jj2]) + xv2[3];
            float ii = sigmoid_hw(ip), ff = sigmoid_hw(fpv);
            float gg = tanh_hw(gp),    oo = sigmoid_hw(op);
            float cn = ff * creg2 + ii * gg;
            creg2 = cn;
            float hn = oo * tanh_hw(cn);
            hN[b2 * HDIM + cta * 16 + jj2] = __float2half(hn);
            if (t == T_STEPS - 1) {
                out[HOFF + (size_t)b2 * HDIM + cta * 16 + jj2] = hn;
                out[COFF + (size_t)b2 * HDIM + cta * 16 + jj2] = cn;
            }
            e2 = exp_hw(hn);
        }
        float v1 = e1, v2 = e2;
        #pragma unroll
        for (int o = 8; o > 0; o >>= 1) {
            v1 += __shfl_xor_sync(0xffffffffu, v1, o);
            v2 += __shfl_xor_sync(0xffffffffu, v2, o);
        }

        bar_target += NCTAS;
        grid_barrier(bar_target);

        if (t + 1 < T_STEPS) {
            const __half* hnext = d_h16[(t + 1) & 1];
            #pragma unroll
            for (int st = 0; st < 5; ++st) ISSUE(st, st * KT, hnext);
        }
        if (t > 0) {
            float s1 = __ldcg(&d_sum[(t - 1) * BATCH + b1]);
            float s2 = __ldcg(&d_sum[(t - 1) * BATCH + b2]);
            out[(size_t)(t - 1) * BATCH * HDIM + (size_t)b1 * HDIM + cta * 16 + jj1] = pe1 * (1.0f / s1);
            out[(size_t)(t - 1) * BATCH * HDIM + (size_t)b2 * HDIM + cta * 16 + jj2] = pe2 * (1.0f / s2);
        }
        if ((lane & 15) == 0) {
            atomicAdd(&d_sum[t * BATCH + b1], v1);
            atomicAdd(&d_sum[t * BATCH + b2], v2);
        }
        pe1 = e1;
        pe2 = e2;
    }

    bar_target += NCTAS;
    grid_barrier(bar_target);
    {
        float s1 = __ldcg(&d_sum[(T_STEPS - 1) * BATCH + b1]);
        float s2 = __ldcg(&d_sum[(T_STEPS - 1) * BATCH + b2]);
        out[(size_t)(T_STEPS - 1) * BATCH * HDIM + (size_t)b1 * HDIM + cta * 16 + jj1] = pe1 * (1.0f / s1);
        out[(size_t)(T_STEPS - 1) * BATCH * HDIM + (size_t)b2 * HDIM + cta * 16 + jj2] = pe2 * (1.0f / s2);
    }
#undef ISSUE
}

// ---------------- entry ----------------
extern "C" void kernel_launch(void* const* d_in, const int* in_sizes, int n_in,
                              void* d_out, int out_size)
{
    (void)in_sizes; (void)n_in; (void)out_size;
    const float* input = (const float*)d_in[0];
    const float* h0    = (const float*)d_in[1];
    const float* c0    = (const float*)d_in[2];
    const float* wih   = (const float*)d_in[3];
    const float* whh   = (const float*)d_in[4];
    const float* bih   = (const float*)d_in[5];
    const float* bhh   = (const float*)d_in[6];

    cudaFuncSetAttribute(xproj_kernel,
                         cudaFuncAttributeMaxDynamicSharedMemorySize, X2SMEM);
    cudaFuncSetAttribute(lstm_persistent_c0,
                         cudaFuncAttributeMaxDynamicSharedMemorySize, PSMEM);

    prep_kernel<<<1024, 256>>>(input, h0, c0, wih, whh, bih, bhh);
    xproj_kernel<<<dim3(G4 / 128, (T_STEPS * BATCH) / 128), X2THREADS, X2SMEM>>>();
    lstm_persistent_c0<<<NCTAS, PTHREADS, PSMEM>>>((float*)d_out, c0);
}

// round 16
// speedup vs baseline: 1.1085x; 1.0809x over previous
#include <cuda_runtime.h>
#include <cuda_fp16.h>
#include <cstdint>

#define T_STEPS 256
#define BATCH   64
#define XDIM    512
#define HDIM    2048
#define G4      8192
#define NCTAS   128
#define PTHREADS 512
#define KT      64                 // K-tile per stage (halfs) = 128 B rows
#define PSTAGES 6                  // persistent-kernel stages
#define ASTG    8192               // persistent stage tile bytes (64 rows * 128 B)
#define GSTR    68                 // persistent gsum row stride (halfs)
#define GSLAB   (64*GSTR)          // halfs per slab

// persistent smem layout (bytes)
#define OFF_SB   (2*PSTAGES*ASTG)            // 98304
#define OFF_GSUM (OFF_SB + 2*PSTAGES*ASTG)   // 196608
#define PSMEM    (OFF_GSUM + 4*GSLAB*2)      // 231424 B

// xproj v2: 128x128 tiles, 512 threads
#define X2THREADS 512
#define XNST    4
#define XASTG   16384
#define XGSTR   132
#define XGSLAB  (128*XGSTR)
#define X2OFF_B (XNST*XASTG)
#define X2OFF_G (2*XNST*XASTG)
#define X2SMEM  (X2OFF_G + 2*XGSLAB*2)

// ---------------- device scratch ----------------
__device__ __align__(16) __half d_in16 [T_STEPS * BATCH * XDIM];
__device__ __align__(16) __half d_wih16[G4 * XDIM];
__device__ __align__(16) __half d_whh16[G4 * HDIM];
__device__ __align__(16) float  d_bsum [G4];
__device__ __align__(16) __half d_xproj[(size_t)T_STEPS * BATCH * G4];
__device__ __align__(16) __half d_h16  [2][BATCH * HDIM];
__device__ __align__(16) float  d_sum  [T_STEPS * BATCH];
__device__ unsigned d_bar;

// ---------------- helpers ----------------
__device__ __forceinline__ void mma16816(float* c,
    uint32_t a0, uint32_t a1, uint32_t a2, uint32_t a3,
    uint32_t b0, uint32_t b1)
{
    asm volatile(
        "mma.sync.aligned.m16n8k16.row.col.f32.f16.f16.f32 "
        "{%0,%1,%2,%3},{%4,%5,%6,%7},{%8,%9},{%0,%1,%2,%3};\n"
        : "+f"(c[0]), "+f"(c[1]), "+f"(c[2]), "+f"(c[3])
        : "r"(a0), "r"(a1), "r"(a2), "r"(a3), "r"(b0), "r"(b1));
}
#define LDSM4(r0, r1, r2, r3, addr) \
    asm volatile("ldmatrix.sync.aligned.m8n8.x4.shared.b16 {%0,%1,%2,%3}, [%4];" \
        : "=r"(r0), "=r"(r1), "=r"(r2), "=r"(r3) : "r"(addr))

__device__ __forceinline__ float tanh_hw(float x) {
    float y;
    asm("tanh.approx.f32 %0, %1;" : "=f"(y) : "f"(x));
    return y;
}
__device__ __forceinline__ float sigmoid_hw(float x) {
    return fmaf(tanh_hw(0.5f * x), 0.5f, 0.5f);
}
__device__ __forceinline__ float exp_hw(float x) {
    float y;
    asm("ex2.approx.ftz.f32 %0, %1;" : "=f"(y) : "f"(x * 1.4426950408889634f));
    return y;
}

__device__ __forceinline__ uint32_t smem_u32(const void* p) {
    return (uint32_t)__cvta_generic_to_shared(p);
}
__device__ __forceinline__ int fperm(int r) { return ((r & 1) << 2) | ((r & 7) >> 1); }

#define CP16(dst_u32, src_ptr) \
    asm volatile("cp.async.cg.shared.global [%0], [%1], 16;\n" :: "r"(dst_u32), "l"(src_ptr))
#define CP_COMMIT() asm volatile("cp.async.commit_group;\n" ::: "memory")
#define CP_WAIT2()  asm volatile("cp.async.wait_group 2;\n" ::: "memory")
#define CP_WAIT4()  asm volatile("cp.async.wait_group 4;\n" ::: "memory")

// row permutation: dst row (CTA-major: cta*64 + gate*16 + jj) -> src gate row
__device__ __forceinline__ int perm_src_row(int r) {
    int cta = r >> 6;
    int ln  = r & 63;
    int gate = ln >> 4;
    int jj   = ln & 15;
    return gate * HDIM + cta * 16 + jj;
}

__device__ __forceinline__ uint2 cvt4(const float4 v) {
    __half2 p0 = __floats2half2_rn(v.x, v.y);
    __half2 p1 = __floats2half2_rn(v.z, v.w);
    return make_uint2(*(uint32_t*)&p0, *(uint32_t*)&p1);
}

// ---------------- phase 0 (vectorized conversions) ----------------
__global__ __launch_bounds__(256) void prep_kernel(
    const float* __restrict__ input, const float* __restrict__ h0,
    const float* __restrict__ c0,    const float* __restrict__ wih,
    const float* __restrict__ whh,   const float* __restrict__ bih,
    const float* __restrict__ bhh)
{
    (void)c0;
    const int i0 = blockIdx.x * blockDim.x + threadIdx.x;
    const int stride = gridDim.x * blockDim.x;
    if (i0 == 0) d_bar = 0u;
    for (int i = i0; i < (T_STEPS * BATCH * XDIM) / 4; i += stride)
        *(uint2*)(d_in16 + i * 4) = cvt4(*(const float4*)(input + i * 4));
    for (int i = i0; i < (G4 * XDIM) / 4; i += stride) {
        int e = i * 4;
        int r = e >> 9, k = e & (XDIM - 1);
        *(uint2*)(d_wih16 + e) =
            cvt4(*(const float4*)(wih + (size_t)perm_src_row(r) * XDIM + k));
    }
    for (int i = i0; i < (G4 * HDIM) / 4; i += stride) {
        size_t e = (size_t)i * 4;
        int r = (int)(e >> 11), k = (int)(e & (HDIM - 1));
        *(uint2*)(d_whh16 + e) =
            cvt4(*(const float4*)(whh + (size_t)perm_src_row(r) * HDIM + k));
    }
    for (int i = i0; i < G4; i += stride) {
        int s = perm_src_row(i);
        d_bsum[i] = bih[s] + bhh[s];
    }
    for (int i = i0; i < (BATCH * HDIM) / 4; i += stride)
        *(uint2*)(&d_h16[0][i * 4]) = cvt4(*(const float4*)(h0 + i * 4));
    for (int i = i0; i < T_STEPS * BATCH; i += stride)
        d_sum[i] = 0.0f;
}

// ---------------- phase 1: xproj v2 — 128x128 tiles, m2 x n4 x k2 ----------------
__global__ __launch_bounds__(X2THREADS) void xproj_kernel()
{
    extern __shared__ __align__(1024) char xsmem_raw[];
    const uint32_t sbase = smem_u32(xsmem_raw);
    const uint32_t sA = sbase;
    const uint32_t sB = sbase + X2OFF_B;
    __half* gsum = (__half*)(xsmem_raw + X2OFF_G);

    const int tid  = threadIdx.x;
    const int lane = tid & 31;
    const int gwid = tid >> 5;
    const int wm = gwid & 1;
    const int wn = (gwid >> 1) & 3;
    const int wk = gwid >> 3;
    const int n0 = blockIdx.x * 128;
    const int m0 = blockIdx.y * 128;

    const int lrow = tid >> 2, lch = tid & 3;
    const int fp_s = fperm(lrow);
    const uint32_t d0 = (uint32_t)(lrow * 128 + ((lch ^ fp_s) << 4));
    const uint32_t d1 = (uint32_t)(lrow * 128 + (((lch + 4) ^ fp_s) << 4));
    const int scol = lch * 8;
    const __half* Ag = d_in16  + (size_t)(m0 + lrow) * XDIM + scol;
    const __half* Bg = d_wih16 + (size_t)(n0 + lrow) * XDIM + scol;

    const int fp_l = fperm(lane & 7);
    uint32_t rowA[4];
    #pragma unroll
    for (int mf = 0; mf < 4; ++mf)
        rowA[mf] = (uint32_t)((wm * 64 + mf * 16 + (lane & 15)) * 128);
    const uint32_t rowB0 = (uint32_t)((wn * 32 + ((lane >> 4) & 1) * 8 + (lane & 7)) * 128);
    const uint32_t rowB1 = rowB0 + 16 * 128;
    const int khA = (lane >> 4) & 1;
    const int khB = (lane >> 3) & 1;
    const int kb16 = wk * 2;

    float acc[4][4][4];
    #pragma unroll
    for (int i = 0; i < 4; i++)
        #pragma unroll
        for (int j = 0; j < 4; j++)
            #pragma unroll
            for (int q = 0; q < 4; q++) acc[i][j][q] = 0.0f;

#define XISSUE(SLOT, KB) do {                                                 \
        const uint32_t ao_ = sA + (uint32_t)(SLOT) * XASTG;                   \
        const uint32_t bo_ = sB + (uint32_t)(SLOT) * XASTG;                   \
        CP16(ao_ + d0, Ag + (KB));                                            \
        CP16(ao_ + d1, Ag + (KB) + 32);                                       \
        CP16(bo_ + d0, Bg + (KB));                                            \
        CP16(bo_ + d1, Bg + (KB) + 32);                                       \
        CP_COMMIT();                                                          \
    } while (0)

    #pragma unroll
    for (int st = 0; st < 3; ++st) XISSUE(st, st * KT);

    const int NITX = XDIM / KT;
    #pragma unroll
    for (int it = 0; it < NITX; ++it) {
        CP_WAIT2();
        __syncthreads();
        const uint32_t At = sA + (uint32_t)((it & 3) * XASTG);
        const uint32_t Bt = sB + (uint32_t)((it & 3) * XASTG);
        #pragma unroll
        for (int kc = 0; kc < 2; ++kc) {
            const uint32_t ccA = (uint32_t)((((kb16 + kc) << 1) | khA) ^ fp_l) << 4;
            const uint32_t ccB = (uint32_t)((((kb16 + kc) << 1) | khB) ^ fp_l) << 4;
            uint32_t a[4][4], bb0[4], bb1[4];
            #pragma unroll
            for (int mf = 0; mf < 4; ++mf)
                LDSM4(a[mf][0], a[mf][1], a[mf][2], a[mf][3], At + rowA[mf] + ccA);
            LDSM4(bb0[0], bb0[1], bb0[2], bb0[3], Bt + rowB0 + ccB);
            LDSM4(bb1[0], bb1[1], bb1[2], bb1[3], Bt + rowB1 + ccB);
            #pragma unroll
            for (int mf = 0; mf < 4; ++mf) {
                mma16816(acc[mf][0], a[mf][0], a[mf][1], a[mf][2], a[mf][3], bb0[0], bb0[1]);
                mma16816(acc[mf][1], a[mf][0], a[mf][1], a[mf][2], a[mf][3], bb0[2], bb0[3]);
                mma16816(acc[mf][2], a[mf][0], a[mf][1], a[mf][2], a[mf][3], bb1[0], bb1[1]);
                mma16816(acc[mf][3], a[mf][0], a[mf][1], a[mf][2], a[mf][3], bb1[2], bb1[3]);
            }
        }
        __syncthreads();
        if (it + 3 < NITX) {
            XISSUE((it + 3) & 3, (it + 3) * KT);
        } else {
            CP_COMMIT();
        }
    }
#undef XISSUE

    {
        __half* gs = gsum + (size_t)wk * XGSLAB;
        const int gq = lane >> 2, tq = lane & 3;
        #pragma unroll
        for (int mf = 0; mf < 4; ++mf) {
            const int row = wm * 64 + mf * 16 + gq;
            #pragma unroll
            for (int nf = 0; nf < 4; ++nf) {
                const int col = wn * 32 + nf * 8 + tq * 2;
                *(__half2*)&gs[row * XGSTR + col] =
                    __floats2half2_rn(acc[mf][nf][0], acc[mf][nf][1]);
                *(__half2*)&gs[(row + 8) * XGSTR + col] =
                    __floats2half2_rn(acc[mf][nf][2], acc[mf][nf][3]);
            }
        }
    }
    __syncthreads();

    {
        const int r  = tid >> 2;
        const int c0 = (tid & 3) * 32;
        const __half* g0 = gsum + (size_t)r * XGSTR + c0;
        const __half* g1 = g0 + XGSLAB;
        __half* dst = d_xproj + (size_t)(m0 + r) * G4 + n0 + c0;
        const float* bs = d_bsum + n0 + c0;
        #pragma unroll
        for (int j = 0; j < 16; ++j) {
            float2 v0 = __half22float2(*(const __half2*)(g0 + 2 * j));
            float2 v1 = __half22float2(*(const __half2*)(g1 + 2 * j));
            float2 bb = *(const float2*)(bs + 2 * j);
            *(__half2*)(dst + 2 * j) =
                __floats2half2_rn(v0.x + v1.x + bb.x, v0.y + v1.y + bb.y);
        }
    }
}

// ---------------- grid barrier (128 CTAs co-resident) ----------------
__device__ __forceinline__ void grid_barrier(unsigned target)
{
    __syncthreads();
    if (threadIdx.x == 0) {
        __threadfence();
        atomicAdd(&d_bar, 1u);
        volatile unsigned* p = &d_bar;
        while (*p < target) { }
        __threadfence();
    }
    __syncthreads();
}

// ---------------- phase 2: persistent recurrent kernel (vectorized pointwise) ----
__global__ __launch_bounds__(PTHREADS, 1) void lstm_persistent_c0(
    float* __restrict__ out, const float* __restrict__ c0)
{
    extern __shared__ __align__(1024) char smem_raw[];
    const uint32_t sbase = smem_u32(smem_raw);
    __half* gsum = (__half*)(smem_raw + OFF_GSUM);

    const int cta  = blockIdx.x;
    const int tid  = threadIdx.x;
    const int lane = tid & 31;
    const int g    = tid >> 8;
    const int gtid = tid & 255;
    const int gwid = gtid >> 5;
    const int wm = gwid & 1;
    const int wn = (gwid >> 1) & 1;
    const int wk = gwid >> 2;
    const int gq = lane >> 2, tq = lane & 3;
    const int n0 = cta * 64;
    const int KOFF = g * (HDIM / 2);
    const int NIT  = (HDIM / 2) / KT;

    const uint32_t aGrp = sbase + (uint32_t)g * PSTAGES * ASTG;
    const uint32_t bGrp = sbase + OFF_SB + (uint32_t)g * PSTAGES * ASTG;

    const int lrow = gtid >> 2, lch = gtid & 3;
    const int fp_s = fperm(lrow);
    const uint32_t d0 = (uint32_t)(lrow * 128 + ((lch ^ fp_s) << 4));
    const uint32_t d1 = (uint32_t)(lrow * 128 + (((lch + 4) ^ fp_s) << 4));
    const int scol = lch * 8;
    const __half* Bg = d_whh16 + (size_t)(n0 + lrow) * HDIM + KOFF + scol;

    const int fp_l = fperm(lane & 7);
    const uint32_t rowA0 = (uint32_t)((wm * 32 + (lane & 15)) * 128);
    const uint32_t rowA1 = rowA0 + 16 * 128;
    const uint32_t rowB0 = (uint32_t)((wn * 32 + ((lane >> 4) & 1) * 8 + (lane & 7)) * 128);
    const uint32_t rowB1 = rowB0 + 16 * 128;
    const int khA = (lane >> 4) & 1;
    const int khB = (lane >> 3) & 1;
    const int kb16 = wk * 2;

    const size_t HOFF = (size_t)T_STEPS * BATCH * HDIM;
    const size_t COFF = HOFF + (size_t)BATCH * HDIM;

    // pointwise mapping: one batch row, two consecutive jj per thread
    const int b  = tid >> 3;
    const int jp = (tid & 7) * 2;
    const int hid = cta * 16 + jp;
    float creg[2];
    {
        float2 cv = *(const float2*)(c0 + (size_t)b * HDIM + hid);
        creg[0] = cv.x; creg[1] = cv.y;
    }
    float pe[2] = {0.0f, 0.0f};
    unsigned bar_target = 0;

#define ISSUE(SLOT, KB, HB) do {                                              \
        const __half* asrc_ = (HB) + (size_t)lrow * HDIM + KOFF + (KB) + scol;\
        const __half* bsrc_ = Bg + (KB);                                      \
        const uint32_t ao_ = aGrp + (uint32_t)(SLOT) * ASTG;                  \
        const uint32_t bo_ = bGrp + (uint32_t)(SLOT) * ASTG;                  \
        CP16(ao_ + d0, asrc_);                                                \
        CP16(ao_ + d1, asrc_ + 32);                                           \
        CP16(bo_ + d0, bsrc_);                                                \
        CP16(bo_ + d1, bsrc_ + 32);                                           \
        CP_COMMIT();                                                          \
    } while (0)

    {
        const __half* hbuf = d_h16[0];
        #pragma unroll
        for (int st = 0; st < 5; ++st) ISSUE(st, st * KT, hbuf);
    }

    #pragma unroll 1
    for (int t = 0; t < T_STEPS; ++t) {
        const __half* hbuf = d_h16[t & 1];

        // prefetch xproj gate values (vectorized, hidden behind GEMM)
        const __half* xr = d_xproj + ((size_t)t * BATCH + b) * G4 + n0;
        float2 xv[4];
        #pragma unroll
        for (int q = 0; q < 4; ++q)
            xv[q] = __half22float2(*(const __half2*)(xr + q * 16 + jp));

        float acc[2][4][4];
        #pragma unroll
        for (int i = 0; i < 2; i++)
            #pragma unroll
            for (int j = 0; j < 4; j++)
                #pragma unroll
                for (int q = 0; q < 4; q++) acc[i][j][q] = 0.0f;

        #pragma unroll
        for (int it = 0; it < NIT; ++it) {
            const int slot = it % PSTAGES;          // const-folded (full unroll)
            CP_WAIT4();
            asm volatile("bar.sync %0, 256;\n" :: "r"(g + 1) : "memory");
            const uint32_t At = aGrp + (uint32_t)(slot * ASTG);
            const uint32_t Bt = bGrp + (uint32_t)(slot * ASTG);
            #pragma unroll
            for (int kc = 0; kc < 2; ++kc) {
                const uint32_t ccA = (uint32_t)((((kb16 + kc) << 1) | khA) ^ fp_l) << 4;
                const uint32_t ccB = (uint32_t)((((kb16 + kc) << 1) | khB) ^ fp_l) << 4;
                uint32_t a0[4], a1[4], bb0[4], bb1[4];
                LDSM4(a0[0], a0[1], a0[2], a0[3], At + rowA0 + ccA);
                LDSM4(a1[0], a1[1], a1[2], a1[3], At + rowA1 + ccA);
                LDSM4(bb0[0], bb0[1], bb0[2], bb0[3], Bt + rowB0 + ccB);
                LDSM4(bb1[0], bb1[1], bb1[2], bb1[3], Bt + rowB1 + ccB);
                mma16816(acc[0][0], a0[0], a0[1], a0[2], a0[3], bb0[0], bb0[1]);
                mma16816(acc[0][1], a0[0], a0[1], a0[2], a0[3], bb0[2], bb0[3]);
                mma16816(acc[0][2], a0[0], a0[1], a0[2], a0[3], bb1[0], bb1[1]);
                mma16816(acc[0][3], a0[0], a0[1], a0[2], a0[3], bb1[2], bb1[3]);
                mma16816(acc[1][0], a1[0], a1[1], a1[2], a1[3], bb0[0], bb0[1]);
                mma16816(acc[1][1], a1[0], a1[1], a1[2], a1[3], bb0[2], bb0[3]);
                mma16816(acc[1][2], a1[0], a1[1], a1[2], a1[3], bb1[0], bb1[1]);
                mma16816(acc[1][3], a1[0], a1[1], a1[2], a1[3], bb1[2], bb1[3]);
            }
            if (it + 5 < NIT) {
                const int wslot = (it + 5) % PSTAGES;   // const-folded
                ISSUE(wslot, (it + 5) * KT, hbuf);
            } else {
                CP_COMMIT();
            }
        }

        {
            __half* gs = gsum + (size_t)(g * 2 + wk) * GSLAB;
            #pragma unroll
            for (int mf = 0; mf < 2; ++mf) {
                const int row = wm * 32 + mf * 16 + gq;
                #pragma unroll
                for (int nf = 0; nf < 4; ++nf) {
                    const int col = wn * 32 + nf * 8 + tq * 2;
                    *(__half2*)&gs[row * GSTR + col] =
                        __floats2half2_rn(acc[mf][nf][0], acc[mf][nf][1]);
                    *(__half2*)&gs[(row + 8) * GSTR + col] =
                        __floats2half2_rn(acc[mf][nf][2], acc[mf][nf][3]);
                }
            }
        }
        __syncthreads();

        // pointwise LSTM + exp — fully vectorized (one b, two jj per thread)
        __half* hN = d_h16[(t + 1) & 1];
        const __half* gb = gsum + (size_t)b * GSTR + jp;
        float2 gs4[4];
        #pragma unroll
        for (int gt = 0; gt < 4; ++gt) {
            float2 s = xv[gt];
            #pragma unroll
            for (int sl = 0; sl < 4; ++sl) {
                float2 v = __half22float2(*(const __half2*)(gb + (size_t)sl * GSLAB + gt * 16));
                s.x += v.x; s.y += v.y;
            }
            gs4[gt] = s;
        }
        float e[2];
        __half hh[2];
        float cc[2];
        #pragma unroll
        for (int k = 0; k < 2; ++k) {
            float ip  = (k == 0) ? gs4[0].x : gs4[0].y;
            float fpv = (k == 0) ? gs4[1].x : gs4[1].y;
            float gp  = (k == 0) ? gs4[2].x : gs4[2].y;
            float op  = (k == 0) ? gs4[3].x : gs4[3].y;
            float ii = sigmoid_hw(ip), ff = sigmoid_hw(fpv);
            float gg = tanh_hw(gp),    oo = sigmoid_hw(op);
            float cn = ff * creg[k] + ii * gg;
            creg[k] = cn;
            cc[k] = cn;
            float hn = oo * tanh_hw(cn);
            hh[k] = __float2half(hn);
            e[k] = exp_hw(hn);
        }
        *(__half2*)(hN + (size_t)b * HDIM + hid) = __halves2half2(hh[0], hh[1]);
        if (t == T_STEPS - 1) {
            float h0f = __half2float(hh[0]), h1f = __half2float(hh[1]);
            *(float2*)(out + HOFF + (size_t)b * HDIM + hid) = make_float2(h0f, h1f);
            *(float2*)(out + COFF + (size_t)b * HDIM + hid) = make_float2(cc[0], cc[1]);
        }
        float v = e[0] + e[1];
        #pragma unroll
        for (int o = 4; o > 0; o >>= 1)
            v += __shfl_xor_sync(0xffffffffu, v, o);

        bar_target += NCTAS;
        grid_barrier(bar_target);

        if (t + 1 < T_STEPS) {
            const __half* hnext = d_h16[(t + 1) & 1];
            #pragma unroll
            for (int st = 0; st < 5; ++st) ISSUE(st, st * KT, hnext);
        }
        if (t > 0) {
            float s = __ldcg(&d_sum[(t - 1) * BATCH + b]);
            float inv = 1.0f / s;
            *(float2*)(out + (size_t)(t - 1) * BATCH * HDIM + (size_t)b * HDIM + hid) =
                make_float2(pe[0] * inv, pe[1] * inv);
        }
        if ((lane & 7) == 0)
            atomicAdd(&d_sum[t * BATCH + b], v);
        pe[0] = e[0];
        pe[1] = e[1];
    }

    bar_target += NCTAS;
    grid_barrier(bar_target);
    {
        float s = __ldcg(&d_sum[(T_STEPS - 1) * BATCH + b]);
        float inv = 1.0f / s;
        *(float2*)(out + (size_t)(T_STEPS - 1) * BATCH * HDIM + (size_t)b * HDIM + hid) =
            make_float2(pe[0] * inv, pe[1] * inv);
    }
#undef ISSUE
}

// ---------------- entry ----------------
extern "C" void kernel_launch(void* const* d_in, const int* in_sizes, int n_in,
                              void* d_out, int out_size)
{
    (void)in_sizes; (void)n_in; (void)out_size;
    const float* input = (const float*)d_in[0];
    const float* h0    = (const float*)d_in[1];
    const float* c0    = (const float*)d_in[2];
    const float* wih   = (const float*)d_in[3];
    const float* whh   = (const float*)d_in[4];
    const float* bih   = (const float*)d_in[5];
    const float* bhh   = (const float*)d_in[6];

    cudaFuncSetAttribute(xproj_kernel,
                         cudaFuncAttributeMaxDynamicSharedMemorySize, X2SMEM);
    cudaFuncSetAttribute(lstm_persistent_c0,
                         cudaFuncAttributeMaxDynamicSharedMemorySize, PSMEM);

    prep_kernel<<<1024, 256>>>(input, h0, c0, wih, whh, bih, bhh);
    xproj_kernel<<<dim3(G4 / 128, (T_STEPS * BATCH) / 128), X2THREADS, X2SMEM>>>();
    lstm_persistent_c0<<<NCTAS, PTHREADS, PSMEM>>>((float*)d_out, c0);
}